// round 9
// baseline (speedup 1.0000x reference)
#include <cuda_runtime.h>
#include <cuda_fp16.h>
#include <cstdint>

// EmbeddingBag(mode='sum') + bias.
// Insight: runtime == total LTS(L2) bytes / ~6300 B/cyc chip cap. So move the
// gather OFF the LTS path entirely: split HIDDEN=256 into 16 column groups;
// a 16-col fp16 slice of the whole 6144-row table is 192KB -> lives in SMEM.
// Grid = 16 col-groups x 9 bag-chunks = 144 CTAs (1 per SM, ~221KB smem).
// Row gathers become LDS (no LTS traffic). Remaining LTS bytes ~93MB.
//
// Phases:
//  A) convert fp32 table -> fp16 in column-group-major layout g_tg[g][row][16]
//  B) compress indices to u16 (rows < 65536)
//  C) column-split gather: per CTA load slice to SMEM (36B/row stride; odd
//     word multiplier 9 => bank starts uniform over 32 banks), then warps
//     process bags: 8 lanes/row x 4 rows/phase, LDS.32, 4 fp16 accumulators,
//     fp32 cross-group reduction via shfl_xor, bias added post-reduce.
// Fallback (rows > 6144 or n_total > capacity): direct fp32 gather.

#define HIDDEN    256
#define MAXR      6144
#define COLG      16      // column groups
#define CG_COLS   16      // columns per group
#define STRIDE_B  36      // smem bytes per row (9 words; odd multiplier)
#define CHUNKS    9       // bag chunks (16*9 = 144 CTAs)
#define IDX_CAP   (1 << 20)

__device__ __half          g_tg[MAXR * HIDDEN];   // col-grouped fp16 table (3MB)
__device__ unsigned short  g_idx16[IDX_CAP];      // compressed indices (2MB)

__device__ __forceinline__ unsigned h2_to_u(__half2 h) {
    unsigned u; memcpy(&u, &h, 4); return u;
}
__device__ __forceinline__ __half2 u_to_h2(unsigned u) {
    __half2 h; memcpy(&h, &u, 4); return h;
}
__device__ __forceinline__ unsigned hadd_u(unsigned a, unsigned b) {
    return h2_to_u(__hadd2(u_to_h2(a), u_to_h2(b)));
}

// ---------------- A: fp32 -> fp16 column-group-major ----------------
// thread t handles 8 consecutive halves (stay within one 16-col group).
__global__ __launch_bounds__(256)
void convert_cg_kernel(const float4* __restrict__ table4, int rows)
{
    int t = blockIdx.x * blockDim.x + threadIdx.x;
    int n8 = rows * HIDDEN / 8;
    if (t >= n8) return;
    int e  = t * 8;
    int r  = e >> 8;            // e / 256
    int c  = e & 255;
    int g  = c >> 4;
    int co = c & 15;            // 0 or 8
    float4 a = __ldg(table4 + 2 * t);
    float4 b = __ldg(table4 + 2 * t + 1);
    uint4 v;
    v.x = h2_to_u(__floats2half2_rn(a.x, a.y));
    v.y = h2_to_u(__floats2half2_rn(a.z, a.w));
    v.z = h2_to_u(__floats2half2_rn(b.x, b.y));
    v.w = h2_to_u(__floats2half2_rn(b.z, b.w));
    reinterpret_cast<uint4*>(g_tg)[(size_t)(g * rows + r) * 2 + (co >> 3)] = v;
}

// ---------------- B: idx -> u16 ----------------
__global__ __launch_bounds__(256)
void idx16_kernel(const int* __restrict__ idx, int n)
{
    int t = blockIdx.x * blockDim.x + threadIdx.x;
    if (t < n) g_idx16[t] = (unsigned short)__ldg(idx + t);
}

// ---------------- C: column-split gather ----------------
__global__ __launch_bounds__(1024)
void embag_cs_kernel(const int* __restrict__ offs,
                     const float* __restrict__ bias,
                     float* __restrict__ out,
                     int batch, int n_total, int rows, int bags_per_chunk)
{
    extern __shared__ unsigned char smem[];
    const int g     = blockIdx.x & 15;
    const int chunk = blockIdx.x >> 4;

    // load this group's 16-col slice: rows x 32B, smem stride 36B.
    {
        const uint4* src = reinterpret_cast<const uint4*>(g_tg) + (size_t)g * rows * 2;
        for (int r = threadIdx.x; r < rows; r += 1024) {
            uint4 q0 = src[2 * r];
            uint4 q1 = src[2 * r + 1];
            unsigned* d = reinterpret_cast<unsigned*>(smem + r * STRIDE_B);
            d[0] = q0.x; d[1] = q0.y; d[2] = q0.z; d[3] = q0.w;
            d[4] = q1.x; d[5] = q1.y; d[6] = q1.z; d[7] = q1.w;
        }
        if (threadIdx.x < 8)
            reinterpret_cast<unsigned*>(smem + rows * STRIDE_B)[threadIdx.x] = 0;  // zero row
    }
    __syncthreads();

    const int wid  = threadIdx.x >> 5;
    const int lane = threadIdx.x & 31;
    const int gr   = lane >> 3;        // row subgroup 0..3
    const int w    = lane & 7;         // word (half2) within the 16-col slice
    const int woff = 4 * w;

    const float2 bv = __ldg(reinterpret_cast<const float2*>(bias) + g * 8 + w);

    const int bag_lo = chunk * bags_per_chunk;
    const int bag_hi = min(bag_lo + bags_per_chunk, batch);

    for (int bag = bag_lo + wid; bag < bag_hi; bag += 32) {
        const int s = __ldg(offs + bag);
        const int e = (bag + 1 < batch) ? __ldg(offs + bag + 1) : n_total;

        float2 f = make_float2(0.f, 0.f);

        for (int c0 = s; c0 < e; c0 += 32) {
            const int nc = min(32, e - c0);
            const unsigned mi = (lane < nc) ? (unsigned)g_idx16[c0 + lane]
                                            : (unsigned)rows;   // zero row
            unsigned ha = 0, hb = 0, hc = 0, hd = 0;
            #define PH(p, H)                                                        \
                do {                                                                \
                    unsigned ri = __shfl_sync(0xffffffffu, mi, 4 * (p) + gr);       \
                    unsigned v  = *reinterpret_cast<const unsigned*>(               \
                                      smem + ri * STRIDE_B + woff);                 \
                    H = hadd_u(H, v);                                               \
                } while (0)
            PH(0, ha); PH(1, hb); PH(2, hc); PH(3, hd);
            PH(4, ha); PH(5, hb); PH(6, hc); PH(7, hd);
            #undef PH
            const unsigned sall = hadd_u(hadd_u(ha, hb), hadd_u(hc, hd));
            const float2 fv = __half22float2(u_to_h2(sall));
            f.x += fv.x; f.y += fv.y;
        }

        // reduce over the 4 row subgroups (lanes ^8, ^16 share w)
        f.x += __shfl_xor_sync(0xffffffffu, f.x, 8);
        f.y += __shfl_xor_sync(0xffffffffu, f.y, 8);
        f.x += __shfl_xor_sync(0xffffffffu, f.x, 16);
        f.y += __shfl_xor_sync(0xffffffffu, f.y, 16);

        if (lane < 8) {
            float2* o2 = reinterpret_cast<float2*>(out + (size_t)bag * HIDDEN + g * CG_COLS);
            o2[w] = make_float2(f.x + bv.x, f.y + bv.y);
        }
    }
}

// ---------------- fallback: direct fp32 gather (generality) ----------------
__global__ __launch_bounds__(256)
void embag_f32_kernel(const int* __restrict__ idx,
                      const int* __restrict__ offs,
                      const float4* __restrict__ table4,
                      const float4* __restrict__ bias4,
                      float4* __restrict__ out4,
                      int batch, int n_total)
{
    const int local = threadIdx.x >> 6;
    const int lane  = threadIdx.x & 63;
    const int bag   = blockIdx.x * 4 + local;
    if (bag >= batch) return;
    const int start = __ldg(offs + bag);
    const int end   = (bag + 1 < batch) ? __ldg(offs + bag + 1) : n_total;
    float4 acc = __ldg(bias4 + lane);
    for (int j = start; j < end; ++j) {
        const int i = __ldg(idx + j);
        const float4 a = __ldg(table4 + (size_t)i * 64 + lane);
        acc.x += a.x; acc.y += a.y; acc.z += a.z; acc.w += a.w;
    }
    out4[(size_t)bag * 64 + lane] = acc;
}

extern "C" void kernel_launch(void* const* d_in, const int* in_sizes, int n_in,
                              void* d_out, int out_size)
{
    const int*    feature_indices = (const int*)d_in[0];
    const int*    offsets         = (const int*)d_in[1];
    const float*  table           = (const float*)d_in[2];
    const float*  bias            = (const float*)d_in[3];
    float*        out             = (float*)d_out;

    const int n_total     = in_sizes[0];
    const int batch       = in_sizes[1];
    const int table_elems = in_sizes[2];
    const int rows        = table_elems / HIDDEN;

    if (rows > MAXR || n_total > IDX_CAP) {
        // general fallback
        embag_f32_kernel<<<(batch + 3) / 4, 256>>>(
            feature_indices, offsets, (const float4*)table,
            (const float4*)bias, (float4*)out, batch, n_total);
        return;
    }

    static int attr_done = 0;
    if (!attr_done) {
        cudaFuncSetAttribute(embag_cs_kernel,
                             cudaFuncAttributeMaxDynamicSharedMemorySize,
                             (MAXR + 1) * STRIDE_B);
        attr_done = 1;
    }

    const int n8 = rows * HIDDEN / 8;
    convert_cg_kernel<<<(n8 + 255) / 256, 256>>>((const float4*)table, rows);
    idx16_kernel<<<(n_total + 255) / 256, 256>>>(feature_indices, n_total);

    const int bags_per_chunk = (batch + CHUNKS - 1) / CHUNKS;
    const int smem_bytes = (rows + 1) * STRIDE_B;
    embag_cs_kernel<<<COLG * CHUNKS, 1024, smem_bytes>>>(
        offsets, bias, out, batch, n_total, rows, bags_per_chunk);
}

// round 10
// speedup vs baseline: 2.8643x; 2.8643x over previous
#include <cuda_runtime.h>
#include <cuda_fp16.h>
#include <cstdint>

// EmbeddingBag(mode='sum') + bias, two-phase with PDL overlap:
//  1) convert fp32 table -> fp16 scratch (triggers programmatic launch)
//  2) gather-sum fp16 rows (one warp per bag, LDG.128, fp16 tree-of-4,
//     fp32 accumulate). Gather is launched with programmatic stream
//     serialization: its CTA dispatch ramp + table-independent prologue
//     (offsets, bias, first index group) overlap the convert kernel;
//     cudaGridDependencySynchronize() guards the first table read.
//
// The gather itself runs at the chip LTS cap (~271MB / ~14TB/s); the only
// remaining headroom was the ~1.9us convert launch overhead, now hidden.

#define HIDDEN   256
#define MAX_ROWS 6144
#define ROW_U4   32   // 256 halves = 512B = 32 uint4 per row

__device__ __half g_table_h[MAX_ROWS * HIDDEN];   // 3 MB scratch

__device__ __forceinline__ unsigned h2_to_u(__half2 h) {
    unsigned u; memcpy(&u, &h, 4); return u;
}
__device__ __forceinline__ __half2 u_to_h2(unsigned u) {
    __half2 h; memcpy(&h, &u, 4); return h;
}

// ---------------- phase 1: fp32 -> fp16 convert ----------------
__global__ __launch_bounds__(256)
void convert_kernel(const float4* __restrict__ table4, int n8)
{
    int t = blockIdx.x * blockDim.x + threadIdx.x;
    if (t < n8) {
        float4 a = __ldg(table4 + 2 * t);
        float4 b = __ldg(table4 + 2 * t + 1);
        uint4 v;
        v.x = h2_to_u(__floats2half2_rn(a.x, a.y));
        v.y = h2_to_u(__floats2half2_rn(a.z, a.w));
        v.z = h2_to_u(__floats2half2_rn(b.x, b.y));
        v.w = h2_to_u(__floats2half2_rn(b.z, b.w));
        reinterpret_cast<uint4*>(g_table_h)[t] = v;
    }
#if __CUDA_ARCH__ >= 900
    cudaTriggerProgrammaticLaunchCompletion();
#endif
}

// ---------------- phase 2: gather-sum ----------------
__device__ __forceinline__ void tree4_acc(float acc[8],
                                          const uint4& v0, const uint4& v1,
                                          const uint4& v2, const uint4& v3)
{
    __half2 s0 = __hadd2(__hadd2(u_to_h2(v0.x), u_to_h2(v1.x)),
                         __hadd2(u_to_h2(v2.x), u_to_h2(v3.x)));
    __half2 s1 = __hadd2(__hadd2(u_to_h2(v0.y), u_to_h2(v1.y)),
                         __hadd2(u_to_h2(v2.y), u_to_h2(v3.y)));
    __half2 s2 = __hadd2(__hadd2(u_to_h2(v0.z), u_to_h2(v1.z)),
                         __hadd2(u_to_h2(v2.z), u_to_h2(v3.z)));
    __half2 s3 = __hadd2(__hadd2(u_to_h2(v0.w), u_to_h2(v1.w)),
                         __hadd2(u_to_h2(v2.w), u_to_h2(v3.w)));
    float2 f0 = __half22float2(s0);
    float2 f1 = __half22float2(s1);
    float2 f2 = __half22float2(s2);
    float2 f3 = __half22float2(s3);
    acc[0] += f0.x; acc[1] += f0.y;
    acc[2] += f1.x; acc[3] += f1.y;
    acc[4] += f2.x; acc[5] += f2.y;
    acc[6] += f3.x; acc[7] += f3.y;
}

__device__ __forceinline__ void one_acc(float acc[8], const uint4& v)
{
    float2 f0 = __half22float2(u_to_h2(v.x));
    float2 f1 = __half22float2(u_to_h2(v.y));
    float2 f2 = __half22float2(u_to_h2(v.z));
    float2 f3 = __half22float2(u_to_h2(v.w));
    acc[0] += f0.x; acc[1] += f0.y;
    acc[2] += f1.x; acc[3] += f1.y;
    acc[4] += f2.x; acc[5] += f2.y;
    acc[6] += f3.x; acc[7] += f3.y;
}

__global__ __launch_bounds__(256)
void embag_h_kernel(const int* __restrict__ idx,
                    const int* __restrict__ offs,
                    const float* __restrict__ bias,
                    float* __restrict__ out,
                    int batch, int n_total)
{
    const int warp = (blockIdx.x * blockDim.x + threadIdx.x) >> 5;
    const int lane = threadIdx.x & 31;
    if (warp >= batch) {
#if __CUDA_ARCH__ >= 900
        cudaGridDependencySynchronize();
#endif
        return;
    }

    // ---- table-independent prologue (overlaps convert via PDL) ----
    const int start = __ldg(offs + warp);
    const int end   = (warp + 1 < batch) ? __ldg(offs + warp + 1) : n_total;

    float acc[8];
    {
        float4 b0 = __ldg(reinterpret_cast<const float4*>(bias) + 2 * lane);
        float4 b1 = __ldg(reinterpret_cast<const float4*>(bias) + 2 * lane + 1);
        acc[0] = b0.x; acc[1] = b0.y; acc[2] = b0.z; acc[3] = b0.w;
        acc[4] = b1.x; acc[5] = b1.y; acc[6] = b1.z; acc[7] = b1.w;
    }

    int j = start;
    int i0 = 0, i1 = 0, i2 = 0, i3 = 0;
    const bool has4 = (j + 4 <= end);
    if (has4) {
        i0 = __ldg(idx + j + 0);
        i1 = __ldg(idx + j + 1);
        i2 = __ldg(idx + j + 2);
        i3 = __ldg(idx + j + 3);
    }

#if __CUDA_ARCH__ >= 900
    cudaGridDependencySynchronize();   // convert must be complete past here
#endif

    const uint4* base = reinterpret_cast<const uint4*>(g_table_h) + lane;

    if (has4) {
        for (; j + 8 <= end; j += 4) {
            const int n0 = __ldg(idx + j + 4);
            const int n1 = __ldg(idx + j + 5);
            const int n2 = __ldg(idx + j + 6);
            const int n3 = __ldg(idx + j + 7);
            const uint4 v0 = base[(size_t)i0 * ROW_U4];
            const uint4 v1 = base[(size_t)i1 * ROW_U4];
            const uint4 v2 = base[(size_t)i2 * ROW_U4];
            const uint4 v3 = base[(size_t)i3 * ROW_U4];
            tree4_acc(acc, v0, v1, v2, v3);
            i0 = n0; i1 = n1; i2 = n2; i3 = n3;
        }
        // drain last full group
        const uint4 v0 = base[(size_t)i0 * ROW_U4];
        const uint4 v1 = base[(size_t)i1 * ROW_U4];
        const uint4 v2 = base[(size_t)i2 * ROW_U4];
        const uint4 v3 = base[(size_t)i3 * ROW_U4];
        tree4_acc(acc, v0, v1, v2, v3);
        j += 4;
    }
    for (; j < end; ++j) {
        const int i = __ldg(idx + j);
        one_acc(acc, base[(size_t)i * ROW_U4]);
    }

    float4* o = reinterpret_cast<float4*>(out + (size_t)warp * HIDDEN) + 2 * lane;
    o[0] = make_float4(acc[0], acc[1], acc[2], acc[3]);
    o[1] = make_float4(acc[4], acc[5], acc[6], acc[7]);
}

extern "C" void kernel_launch(void* const* d_in, const int* in_sizes, int n_in,
                              void* d_out, int out_size)
{
    const int*    feature_indices = (const int*)d_in[0];
    const int*    offsets         = (const int*)d_in[1];
    const float4* table4          = (const float4*)d_in[2];
    const float*  bias            = (const float*)d_in[3];
    float*        out             = (float*)d_out;

    const int n_total     = in_sizes[0];
    const int batch       = in_sizes[1];
    const int table_elems = in_sizes[2];
    const int n8          = table_elems / 8;

    convert_kernel<<<(n8 + 255) / 256, 256>>>(table4, n8);

    // Gather with Programmatic Dependent Launch: dispatch ramp + prologue
    // overlap the convert kernel; gridDependencySynchronize guards the
    // first fp16-table read.
    const int warps_per_block = 256 / 32;
    const int grid = (batch + warps_per_block - 1) / warps_per_block;

    cudaLaunchConfig_t cfg = {};
    cfg.gridDim  = dim3(grid, 1, 1);
    cfg.blockDim = dim3(256, 1, 1);
    cfg.dynamicSmemBytes = 0;
    cfg.stream = 0;
    cudaLaunchAttribute attrs[1];
    attrs[0].id = cudaLaunchAttributeProgrammaticStreamSerialization;
    attrs[0].val.programmaticStreamSerializationAllowed = 1;
    cfg.attrs = attrs;
    cfg.numAttrs = 1;

    cudaLaunchKernelEx(&cfg, embag_h_kernel,
                       feature_indices, offsets, bias, out, batch, n_total);
}